// round 7
// baseline (speedup 1.0000x reference)
#include <cuda_runtime.h>
#include <cuda_bf16.h>
#include <math.h>
#include <stdint.h>

#define NF    32
#define NB    2048
#define NK    64
#define NH    64
#define PAIRS 496
#define VSTR  68     // sV row stride in floats
#define ZROW  32     // zero row for padded pairs

// Pre-packed W fragment table (permuted-k): [ks(4)][nt(8)][lane(32)]
__device__ uint2  g_wfrag[4 * 8 * 32];
// Pre-computed pair table: (i,j) per pair, padded pairs -> ZROW
__device__ uchar2 g_pairs[512];

__device__ __forceinline__ uint32_t pack_bf16x2(float lo, float hi) {
    __nv_bfloat162 h = __floats2bfloat162_rn(lo, hi);
    return *reinterpret_cast<uint32_t*>(&h);
}
__device__ __forceinline__ float2 unpack_bf16x2(uint32_t u) {
    __nv_bfloat162 h = *reinterpret_cast<__nv_bfloat162*>(&u);
    return __bfloat1622float2(h);
}

__device__ __forceinline__ void mma_bf16(float& d0, float& d1, float& d2, float& d3,
                                         uint32_t a0, uint32_t a1, uint32_t a2, uint32_t a3,
                                         uint32_t b0, uint32_t b1) {
    asm volatile(
        "mma.sync.aligned.m16n8k16.row.col.f32.bf16.bf16.f32 "
        "{%0,%1,%2,%3}, {%4,%5,%6,%7}, {%8,%9}, {%0,%1,%2,%3};"
        : "+f"(d0), "+f"(d1), "+f"(d2), "+f"(d3)
        : "r"(a0), "r"(a1), "r"(a2), "r"(a3), "r"(b0), "r"(b1));
}

// ---- pre-kernel: W fragments (k-permuted) + pair table ----
__global__ void prep_build(const float* __restrict__ at_w) {
    int idx = blockIdx.x * 256 + threadIdx.x;   // 0..1023
    {
        int lane = idx & 31;
        int tile = idx >> 5;
        int ks = tile >> 3, nt = tile & 7;
        int tig = lane & 3, gid = lane >> 2;
        int lk = ks * 16 + 4 * tig;
        int h  = nt * 8 + gid;
        uint2 v;
        v.x = pack_bf16x2(at_w[lk * NH + h],       at_w[(lk + 1) * NH + h]);
        v.y = pack_bf16x2(at_w[(lk + 2) * NH + h], at_w[(lk + 3) * NH + h]);
        g_wfrag[idx] = v;
    }
    if (idx < 512) {
        uchar2 pr;
        if (idx < PAIRS) {
            int pp = idx, i = 0, off = 0;
            while (pp >= off + (NF - 1 - i)) { off += NF - 1 - i; i++; }
            pr.x = (unsigned char)i;
            pr.y = (unsigned char)(i + 1 + pp - off);
        } else {
            pr.x = ZROW; pr.y = ZROW;
        }
        g_pairs[idx] = pr;
    }
}

__global__ __launch_bounds__(256, 3)
void afm_mma_kernel(const int*   __restrict__ x,      // [F, B]
                    const float* __restrict__ emb_v,  // [VOCAB, K]
                    const float* __restrict__ at_b,   // [H]
                    const float* __restrict__ at_h,   // [H]
                    const float* __restrict__ pvec,   // [K]
                    const float* __restrict__ w0,     // scalar
                    const float* __restrict__ w1,     // [VOCAB]
                    float*       __restrict__ out)    // [B]
{
    __shared__ float  sV[(NF + 1) * VSTR];
    __shared__ float4 sBA4[32];
    __shared__ float  sPool[8][NK];
    __shared__ float  sFm1, sRed[2];

    const int tid  = threadIdx.x;
    const int b    = blockIdx.x;
    const int w    = tid >> 5;
    const int lane = tid & 31;
    const int gid  = lane >> 2;
    const int tig  = lane & 3;

    // ---- zero row ----
    if (tid < NK) sV[ZROW * VSTR + tid] = 0.f;

    // ---- bias/at_h fragment table ----
    if (tid < 32) {
        int nt = tid >> 2, tg = tid & 3;
        int h0 = nt * 8 + 2 * tg;
        sBA4[tid] = make_float4(__ldg(&at_b[h0]),     __ldg(&at_h[h0]),
                                __ldg(&at_b[h0 + 1]), __ldg(&at_h[h0 + 1]));
    }

    // ---- gather embeddings ----
    for (int idx = tid; idx < NF * (NK / 4); idx += 256) {
        int f = idx >> 4, q = idx & 15;
        int row = __ldg(&x[f * NB + b]);
        *(float4*)&sV[f * VSTR + q * 4] = __ldg(&((const float4*)emb_v)[row * 16 + q]);
    }

    // ---- first-order FM ----
    if (tid < NF) {
        int row = __ldg(&x[tid * NB + b]);
        float v = __ldg(&w1[row]);
        #pragma unroll
        for (int off = 16; off >= 1; off >>= 1)
            v += __shfl_xor_sync(0xffffffffu, v, off);
        if (tid == 0) sFm1 = v + __ldg(w0);
    }
    __syncthreads();

    float pooled[16];
    #pragma unroll
    for (int s = 0; s < 16; s++) pooled[s] = 0.f;

    const int kbase = 4 * tig;

    #pragma unroll
    for (int t = 0; t < 4; t++) {
        const int p1 = t * 128 + w * 16 + gid;
        const uchar2 pr1 = __ldg(&g_pairs[p1]);
        const uchar2 pr2 = __ldg(&g_pairs[p1 + 8]);
        const float* ri1 = &sV[pr1.x * VSTR + kbase];
        const float* rj1 = &sV[pr1.y * VSTR + kbase];
        const float* ri2 = &sV[pr2.x * VSTR + kbase];
        const float* rj2 = &sV[pr2.y * VSTR + kbase];

        // ---- A fragments: float4 loads, VV products, bf16 pack ----
        uint32_t af[4][4];
        #pragma unroll
        for (int ks = 0; ks < 4; ks++) {
            const int ko = ks * 16;
            float4 vi = *(const float4*)(ri1 + ko);
            float4 vj = *(const float4*)(rj1 + ko);
            float4 a1v = make_float4(vi.x * vj.x, vi.y * vj.y, vi.z * vj.z, vi.w * vj.w);
            vi = *(const float4*)(ri2 + ko);
            vj = *(const float4*)(rj2 + ko);
            float4 a2v = make_float4(vi.x * vj.x, vi.y * vj.y, vi.z * vj.z, vi.w * vj.w);
            af[ks][0] = pack_bf16x2(a1v.x, a1v.y);
            af[ks][2] = pack_bf16x2(a1v.z, a1v.w);
            af[ks][1] = pack_bf16x2(a2v.x, a2v.y);
            af[ks][3] = pack_bf16x2(a2v.z, a2v.w);
        }

        // ---- GEMM (W from L1-resident global) + fused score epilogue ----
        float s1 = 0.f, s2 = 0.f;
        #pragma unroll
        for (int nt = 0; nt < 8; nt++) {
            float d0 = 0.f, d1 = 0.f, d2 = 0.f, d3 = 0.f;
            #pragma unroll
            for (int ks = 0; ks < 4; ks++) {
                uint2 wv = __ldg(&g_wfrag[(ks * 8 + nt) * 32 + lane]);
                mma_bf16(d0, d1, d2, d3,
                         af[ks][0], af[ks][1], af[ks][2], af[ks][3],
                         wv.x, wv.y);
            }
            float4 ba = sBA4[nt * 4 + tig];   // broadcast LDS.128
            s1 += fmaxf(d0 + ba.x, 0.f) * ba.y + fmaxf(d1 + ba.z, 0.f) * ba.w;
            s2 += fmaxf(d2 + ba.x, 0.f) * ba.y + fmaxf(d3 + ba.z, 0.f) * ba.w;
        }
        s1 += __shfl_xor_sync(0xffffffffu, s1, 1);
        s1 += __shfl_xor_sync(0xffffffffu, s1, 2);
        s2 += __shfl_xor_sync(0xffffffffu, s2, 1);
        s2 += __shfl_xor_sync(0xffffffffu, s2, 2);

        // ---- pooling from the same A registers ----
        #pragma unroll
        for (int ks = 0; ks < 4; ks++) {
            float2 v;
            v = unpack_bf16x2(af[ks][0]);
            pooled[ks * 4 + 0] = fmaf(s1, v.x, pooled[ks * 4 + 0]);
            pooled[ks * 4 + 1] = fmaf(s1, v.y, pooled[ks * 4 + 1]);
            v = unpack_bf16x2(af[ks][2]);
            pooled[ks * 4 + 2] = fmaf(s1, v.x, pooled[ks * 4 + 2]);
            pooled[ks * 4 + 3] = fmaf(s1, v.y, pooled[ks * 4 + 3]);
            v = unpack_bf16x2(af[ks][1]);
            pooled[ks * 4 + 0] = fmaf(s2, v.x, pooled[ks * 4 + 0]);
            pooled[ks * 4 + 1] = fmaf(s2, v.y, pooled[ks * 4 + 1]);
            v = unpack_bf16x2(af[ks][3]);
            pooled[ks * 4 + 2] = fmaf(s2, v.x, pooled[ks * 4 + 2]);
            pooled[ks * 4 + 3] = fmaf(s2, v.y, pooled[ks * 4 + 3]);
        }
    }

    // ---- reduce pooled across gid lanes ----
    #pragma unroll
    for (int s = 0; s < 16; s++) {
        pooled[s] += __shfl_xor_sync(0xffffffffu, pooled[s], 4);
        pooled[s] += __shfl_xor_sync(0xffffffffu, pooled[s], 8);
        pooled[s] += __shfl_xor_sync(0xffffffffu, pooled[s], 16);
    }
    if (gid == 0) {
        #pragma unroll
        for (int ks = 0; ks < 4; ks++)
            *(float4*)&sPool[w][ks * 16 + 4 * tig] =
                make_float4(pooled[ks * 4 + 0], pooled[ks * 4 + 1],
                            pooled[ks * 4 + 2], pooled[ks * 4 + 3]);
    }
    __syncthreads();

    // ---- final: at_fm = (sum_w pooled) . p ; logit ; sigmoid ----
    if (tid < NK) {
        float v = 0.f;
        #pragma unroll
        for (int g = 0; g < 8; g++) v += sPool[g][tid];
        v *= __ldg(&pvec[tid]);
        #pragma unroll
        for (int off = 16; off >= 1; off >>= 1)
            v += __shfl_xor_sync(0xffffffffu, v, off);
        if ((tid & 31) == 0) sRed[tid >> 5] = v;
    }
    __syncthreads();

    if (tid == 0) {
        float logit = sRed[0] + sRed[1] + sFm1;
        out[b] = 1.f / (1.f + expf(-logit));
    }
}

extern "C" void kernel_launch(void* const* d_in, const int* in_sizes, int n_in,
                              void* d_out, int out_size) {
    const int*   x     = (const int*)  d_in[0];
    const float* emb_v = (const float*)d_in[1];
    const float* at_w  = (const float*)d_in[2];
    const float* at_b  = (const float*)d_in[3];
    const float* at_h  = (const float*)d_in[4];
    const float* pvec  = (const float*)d_in[5];
    const float* w0    = (const float*)d_in[6];
    const float* w1    = (const float*)d_in[7];
    float* out = (float*)d_out;

    prep_build<<<4, 256>>>(at_w);
    afm_mma_kernel<<<NB, 256>>>(x, emb_v, at_b, at_h, pvec, w0, w1, out);
}

// round 8
// speedup vs baseline: 1.0536x; 1.0536x over previous
#include <cuda_runtime.h>
#include <cuda_bf16.h>
#include <math.h>
#include <stdint.h>

#define NF    32
#define NB    2048
#define NK    64
#define NH    64
#define PAIRS 496
#define VSTRU 34     // sV row stride in uints (bf16x2), even for LDS.64 align
#define ZROW  32     // zero row for padded pairs

// Pre-packed W fragment table (permuted-k): [ks(4)][nt(8)][lane(32)]
__device__ uint2  g_wfrag[4 * 8 * 32];
__device__ uchar2 g_pairs[512];

__device__ __forceinline__ uint32_t pack_bf16x2(float lo, float hi) {
    __nv_bfloat162 h = __floats2bfloat162_rn(lo, hi);
    return *reinterpret_cast<uint32_t*>(&h);
}
__device__ __forceinline__ float2 unpack_bf16x2(uint32_t u) {
    __nv_bfloat162 h = *reinterpret_cast<__nv_bfloat162*>(&u);
    return __bfloat1622float2(h);
}
__device__ __forceinline__ uint32_t mul_bf16x2(uint32_t a, uint32_t b) {
    __nv_bfloat162 ha = *reinterpret_cast<__nv_bfloat162*>(&a);
    __nv_bfloat162 hb = *reinterpret_cast<__nv_bfloat162*>(&b);
    __nv_bfloat162 hc = __hmul2(ha, hb);
    return *reinterpret_cast<uint32_t*>(&hc);
}

__device__ __forceinline__ void mma_bf16(float& d0, float& d1, float& d2, float& d3,
                                         uint32_t a0, uint32_t a1, uint32_t a2, uint32_t a3,
                                         uint32_t b0, uint32_t b1) {
    asm volatile(
        "mma.sync.aligned.m16n8k16.row.col.f32.bf16.bf16.f32 "
        "{%0,%1,%2,%3}, {%4,%5,%6,%7}, {%8,%9}, {%0,%1,%2,%3};"
        : "+f"(d0), "+f"(d1), "+f"(d2), "+f"(d3)
        : "r"(a0), "r"(a1), "r"(a2), "r"(a3), "r"(b0), "r"(b1));
}

// ---- pre-kernel: W fragments (k-permuted) + pair table ----
__global__ void prep_build(const float* __restrict__ at_w) {
    int idx = blockIdx.x * 256 + threadIdx.x;   // 0..1023
    {
        int lane = idx & 31;
        int tile = idx >> 5;
        int ks = tile >> 3, nt = tile & 7;
        int tig = lane & 3, gid = lane >> 2;
        int lk = ks * 16 + 4 * tig;
        int h  = nt * 8 + gid;
        uint2 v;
        v.x = pack_bf16x2(at_w[lk * NH + h],       at_w[(lk + 1) * NH + h]);
        v.y = pack_bf16x2(at_w[(lk + 2) * NH + h], at_w[(lk + 3) * NH + h]);
        g_wfrag[idx] = v;
    }
    if (idx < 512) {
        uchar2 pr;
        if (idx < PAIRS) {
            int pp = idx, i = 0, off = 0;
            while (pp >= off + (NF - 1 - i)) { off += NF - 1 - i; i++; }
            pr.x = (unsigned char)i;
            pr.y = (unsigned char)(i + 1 + pp - off);
        } else {
            pr.x = ZROW; pr.y = ZROW;
        }
        g_pairs[idx] = pr;
    }
}

__global__ __launch_bounds__(256, 3)
void afm_mma_kernel(const int*   __restrict__ x,      // [F, B]
                    const float* __restrict__ emb_v,  // [VOCAB, K]
                    const float* __restrict__ at_b,   // [H]
                    const float* __restrict__ at_h,   // [H]
                    const float* __restrict__ pvec,   // [K]
                    const float* __restrict__ w0,     // scalar
                    const float* __restrict__ w1,     // [VOCAB]
                    float*       __restrict__ out)    // [B]
{
    __shared__ uint32_t sVh[(NF + 1) * VSTRU];   // bf16x2 embeddings + zero row
    __shared__ uint2    sWf[1024];               // 8 KB W fragments
    __shared__ uchar2   sPr[512];                // pair table
    __shared__ float4   sBA4[32];
    __shared__ float    sPool[8][NK];
    __shared__ float    sFm1, sRed[2];

    const int tid  = threadIdx.x;
    const int b    = blockIdx.x;
    const int w    = tid >> 5;
    const int lane = tid & 31;
    const int gid  = lane >> 2;
    const int tig  = lane & 3;

    // ---- copy W fragments + pairs into smem ----
    #pragma unroll
    for (int i = tid; i < 1024; i += 256) sWf[i] = g_wfrag[i];
    #pragma unroll
    for (int i = tid; i < 512; i += 256) sPr[i] = g_pairs[i];

    // ---- zero row ----
    if (tid < VSTRU) sVh[ZROW * VSTRU + tid] = 0u;

    // ---- bias/at_h fragment table ----
    if (tid < 32) {
        int nt = tid >> 2, tg = tid & 3;
        int h0 = nt * 8 + 2 * tg;
        sBA4[tid] = make_float4(__ldg(&at_b[h0]),     __ldg(&at_h[h0]),
                                __ldg(&at_b[h0 + 1]), __ldg(&at_h[h0 + 1]));
    }

    // ---- gather embeddings, convert to bf16 ----
    for (int idx = tid; idx < NF * 16; idx += 256) {
        int f = idx >> 4, q = idx & 15;       // 16 float4-chunks per row
        int row = __ldg(&x[f * NB + b]);
        float4 v = __ldg(&((const float4*)emb_v)[row * 16 + q]);
        uint2 pk;
        pk.x = pack_bf16x2(v.x, v.y);
        pk.y = pack_bf16x2(v.z, v.w);
        *(uint2*)&sVh[f * VSTRU + 2 * q] = pk;
    }

    // ---- first-order FM ----
    if (tid < NF) {
        int row = __ldg(&x[tid * NB + b]);
        float v = __ldg(&w1[row]);
        #pragma unroll
        for (int off = 16; off >= 1; off >>= 1)
            v += __shfl_xor_sync(0xffffffffu, v, off);
        if (tid == 0) sFm1 = v + __ldg(w0);
    }
    __syncthreads();

    float pooled[16];
    #pragma unroll
    for (int s = 0; s < 16; s++) pooled[s] = 0.f;

    const int ub = 2 * tig;   // uint offset of logical k = 4*tig

    #pragma unroll
    for (int t = 0; t < 4; t++) {
        const int p1 = t * 128 + w * 16 + gid;
        const uchar2 pr1 = sPr[p1];
        const uchar2 pr2 = sPr[p1 + 8];
        const uint32_t* ri1 = &sVh[pr1.x * VSTRU + ub];
        const uint32_t* rj1 = &sVh[pr1.y * VSTRU + ub];
        const uint32_t* ri2 = &sVh[pr2.x * VSTRU + ub];
        const uint32_t* rj2 = &sVh[pr2.y * VSTRU + ub];

        // ---- A fragments: bf16 loads + bf16x2 products ----
        uint32_t af[4][4];
        #pragma unroll
        for (int ks = 0; ks < 4; ks++) {
            uint2 vi = *(const uint2*)(ri1 + ks * 8);
            uint2 vj = *(const uint2*)(rj1 + ks * 8);
            af[ks][0] = mul_bf16x2(vi.x, vj.x);
            af[ks][2] = mul_bf16x2(vi.y, vj.y);
            vi = *(const uint2*)(ri2 + ks * 8);
            vj = *(const uint2*)(rj2 + ks * 8);
            af[ks][1] = mul_bf16x2(vi.x, vj.x);
            af[ks][3] = mul_bf16x2(vi.y, vj.y);
        }

        // ---- GEMM (W from smem) + fused score epilogue ----
        float s1 = 0.f, s2 = 0.f;
        #pragma unroll
        for (int nt = 0; nt < 8; nt++) {
            float d0 = 0.f, d1 = 0.f, d2 = 0.f, d3 = 0.f;
            #pragma unroll
            for (int ks = 0; ks < 4; ks++) {
                uint2 wv = sWf[(ks * 8 + nt) * 32 + lane];
                mma_bf16(d0, d1, d2, d3,
                         af[ks][0], af[ks][1], af[ks][2], af[ks][3],
                         wv.x, wv.y);
            }
            float4 ba = sBA4[nt * 4 + tig];
            s1 += fmaxf(d0 + ba.x, 0.f) * ba.y + fmaxf(d1 + ba.z, 0.f) * ba.w;
            s2 += fmaxf(d2 + ba.x, 0.f) * ba.y + fmaxf(d3 + ba.z, 0.f) * ba.w;
        }
        s1 += __shfl_xor_sync(0xffffffffu, s1, 1);
        s1 += __shfl_xor_sync(0xffffffffu, s1, 2);
        s2 += __shfl_xor_sync(0xffffffffu, s2, 1);
        s2 += __shfl_xor_sync(0xffffffffu, s2, 2);

        // ---- pooling from the same A registers ----
        #pragma unroll
        for (int ks = 0; ks < 4; ks++) {
            float2 v;
            v = unpack_bf16x2(af[ks][0]);
            pooled[ks * 4 + 0] = fmaf(s1, v.x, pooled[ks * 4 + 0]);
            pooled[ks * 4 + 1] = fmaf(s1, v.y, pooled[ks * 4 + 1]);
            v = unpack_bf16x2(af[ks][2]);
            pooled[ks * 4 + 2] = fmaf(s1, v.x, pooled[ks * 4 + 2]);
            pooled[ks * 4 + 3] = fmaf(s1, v.y, pooled[ks * 4 + 3]);
            v = unpack_bf16x2(af[ks][1]);
            pooled[ks * 4 + 0] = fmaf(s2, v.x, pooled[ks * 4 + 0]);
            pooled[ks * 4 + 1] = fmaf(s2, v.y, pooled[ks * 4 + 1]);
            v = unpack_bf16x2(af[ks][3]);
            pooled[ks * 4 + 2] = fmaf(s2, v.x, pooled[ks * 4 + 2]);
            pooled[ks * 4 + 3] = fmaf(s2, v.y, pooled[ks * 4 + 3]);
        }
    }

    // ---- reduce pooled across gid lanes ----
    #pragma unroll
    for (int s = 0; s < 16; s++) {
        pooled[s] += __shfl_xor_sync(0xffffffffu, pooled[s], 4);
        pooled[s] += __shfl_xor_sync(0xffffffffu, pooled[s], 8);
        pooled[s] += __shfl_xor_sync(0xffffffffu, pooled[s], 16);
    }
    if (gid == 0) {
        #pragma unroll
        for (int ks = 0; ks < 4; ks++)
            *(float4*)&sPool[w][ks * 16 + 4 * tig] =
                make_float4(pooled[ks * 4 + 0], pooled[ks * 4 + 1],
                            pooled[ks * 4 + 2], pooled[ks * 4 + 3]);
    }
    __syncthreads();

    // ---- final: at_fm = (sum_w pooled) . p ; logit ; sigmoid ----
    if (tid < NK) {
        float v = 0.f;
        #pragma unroll
        for (int g = 0; g < 8; g++) v += sPool[g][tid];
        v *= __ldg(&pvec[tid]);
        #pragma unroll
        for (int off = 16; off >= 1; off >>= 1)
            v += __shfl_xor_sync(0xffffffffu, v, off);
        if ((tid & 31) == 0) sRed[tid >> 5] = v;
    }
    __syncthreads();

    if (tid == 0) {
        float logit = sRed[0] + sRed[1] + sFm1;
        out[b] = 1.f / (1.f + expf(-logit));
    }
}

extern "C" void kernel_launch(void* const* d_in, const int* in_sizes, int n_in,
                              void* d_out, int out_size) {
    const int*   x     = (const int*)  d_in[0];
    const float* emb_v = (const float*)d_in[1];
    const float* at_w  = (const float*)d_in[2];
    const float* at_b  = (const float*)d_in[3];
    const float* at_h  = (const float*)d_in[4];
    const float* pvec  = (const float*)d_in[5];
    const float* w0    = (const float*)d_in[6];
    const float* w1    = (const float*)d_in[7];
    float* out = (float*)d_out;

    prep_build<<<4, 256>>>(at_w);
    afm_mma_kernel<<<NB, 256>>>(x, emb_v, at_b, at_h, pvec, w0, w1, out);
}

// round 9
// speedup vs baseline: 1.5682x; 1.4884x over previous
#include <cuda_runtime.h>
#include <cuda_bf16.h>
#include <math.h>
#include <stdint.h>

#define NF    32
#define NB    2048
#define NK    64
#define NH    64
#define PAIRS 496
#define VSTRU 40     // sV row stride in uints (bf16x2): 8-bank row shift, uint2-aligned
#define ZROW  32     // zero row for padded pairs

// Pre-packed W fragment table (permuted-k): [ks(4)][nt(8)][lane(32)]
__device__ uint2 g_wfrag[4 * 8 * 32];

__device__ __forceinline__ uint32_t pack_bf16x2(float lo, float hi) {
    __nv_bfloat162 h = __floats2bfloat162_rn(lo, hi);
    return *reinterpret_cast<uint32_t*>(&h);
}
__device__ __forceinline__ float2 unpack_bf16x2(uint32_t u) {
    __nv_bfloat162 h = *reinterpret_cast<__nv_bfloat162*>(&u);
    return __bfloat1622float2(h);
}
__device__ __forceinline__ uint32_t mul_bf16x2(uint32_t a, uint32_t b) {
    __nv_bfloat162 ha = *reinterpret_cast<__nv_bfloat162*>(&a);
    __nv_bfloat162 hb = *reinterpret_cast<__nv_bfloat162*>(&b);
    __nv_bfloat162 hc = __hmul2(ha, hb);
    return *reinterpret_cast<uint32_t*>(&hc);
}

__device__ __forceinline__ void mma_bf16(float& d0, float& d1, float& d2, float& d3,
                                         uint32_t a0, uint32_t a1, uint32_t a2, uint32_t a3,
                                         uint32_t b0, uint32_t b1) {
    asm volatile(
        "mma.sync.aligned.m16n8k16.row.col.f32.bf16.bf16.f32 "
        "{%0,%1,%2,%3}, {%4,%5,%6,%7}, {%8,%9}, {%0,%1,%2,%3};"
        : "+f"(d0), "+f"(d1), "+f"(d2), "+f"(d3)
        : "r"(a0), "r"(a1), "r"(a2), "r"(a3), "r"(b0), "r"(b1));
}

// ---- pre-kernel: pack W with the k-permutation ----
__global__ void wfrag_build(const float* __restrict__ at_w) {
    int idx  = blockIdx.x * 256 + threadIdx.x;   // 0..1023
    int lane = idx & 31;
    int tile = idx >> 5;
    int ks = tile >> 3, nt = tile & 7;
    int tig = lane & 3, gid = lane >> 2;
    int lk = ks * 16 + 4 * tig;
    int h  = nt * 8 + gid;
    uint2 v;
    v.x = pack_bf16x2(at_w[lk * NH + h],       at_w[(lk + 1) * NH + h]);
    v.y = pack_bf16x2(at_w[(lk + 2) * NH + h], at_w[(lk + 3) * NH + h]);
    g_wfrag[idx] = v;
}

__global__ __launch_bounds__(256, 2)
void afm_mma_kernel(const int*   __restrict__ x,      // [F, B]
                    const float* __restrict__ emb_v,  // [VOCAB, K]
                    const float* __restrict__ at_b,   // [H]
                    const float* __restrict__ at_h,   // [H]
                    const float* __restrict__ pvec,   // [K]
                    const float* __restrict__ w0,     // scalar
                    const float* __restrict__ w1,     // [VOCAB]
                    float*       __restrict__ out)    // [B]
{
    __shared__ uint32_t sVh[(NF + 1) * VSTRU];   // bf16x2 embeddings + zero row
    __shared__ float4   sBA4[32];
    __shared__ unsigned char sI[512], sJ[512];
    __shared__ float    sPool[8][NK];
    __shared__ float    sFm1, sRed[2];

    const int tid  = threadIdx.x;
    const int b    = blockIdx.x;
    const int w    = tid >> 5;
    const int lane = tid & 31;
    const int gid  = lane >> 2;
    const int tig  = lane & 3;

    // ---- W fragments: registers for the whole kernel (proven best in R6) ----
    uint2 Wb[4][8];
    #pragma unroll
    for (int ks = 0; ks < 4; ks++)
        #pragma unroll
        for (int nt = 0; nt < 8; nt++)
            Wb[ks][nt] = __ldg(&g_wfrag[(ks * 8 + nt) * 32 + lane]);

    // ---- pair (i,j) table; padded pairs -> zero row ----
    for (int p = tid; p < 512; p += 256) {
        if (p < PAIRS) {
            int pp = p, i = 0, off = 0;
            while (pp >= off + (NF - 1 - i)) { off += NF - 1 - i; i++; }
            sI[p] = (unsigned char)i;
            sJ[p] = (unsigned char)(i + 1 + pp - off);
        } else {
            sI[p] = ZROW; sJ[p] = ZROW;
        }
    }

    // ---- zero row ----
    if (tid < VSTRU) sVh[ZROW * VSTRU + tid] = 0u;

    // ---- bias/at_h fragment table ----
    if (tid < 32) {
        int nt = tid >> 2, tg = tid & 3;
        int h0 = nt * 8 + 2 * tg;
        sBA4[tid] = make_float4(__ldg(&at_b[h0]),     __ldg(&at_h[h0]),
                                __ldg(&at_b[h0 + 1]), __ldg(&at_h[h0 + 1]));
    }

    // ---- gather embeddings, convert to bf16 ----
    for (int idx = tid; idx < NF * 16; idx += 256) {
        int f = idx >> 4, q = idx & 15;
        int row = __ldg(&x[f * NB + b]);
        float4 v = __ldg(&((const float4*)emb_v)[row * 16 + q]);
        uint2 pk;
        pk.x = pack_bf16x2(v.x, v.y);
        pk.y = pack_bf16x2(v.z, v.w);
        *(uint2*)&sVh[f * VSTRU + 2 * q] = pk;
    }

    // ---- first-order FM ----
    if (tid < NF) {
        int row = __ldg(&x[tid * NB + b]);
        float v = __ldg(&w1[row]);
        #pragma unroll
        for (int off = 16; off >= 1; off >>= 1)
            v += __shfl_xor_sync(0xffffffffu, v, off);
        if (tid == 0) sFm1 = v + __ldg(w0);
    }
    __syncthreads();

    float pooled[16];
    #pragma unroll
    for (int s = 0; s < 16; s++) pooled[s] = 0.f;

    const int ub = 2 * tig;   // uint offset of logical k = 4*tig within ks-block

    #pragma unroll
    for (int t = 0; t < 4; t++) {
        const int p1 = t * 128 + w * 16 + gid;
        const uint32_t* ri1 = &sVh[sI[p1] * VSTRU + ub];
        const uint32_t* rj1 = &sVh[sJ[p1] * VSTRU + ub];
        const uint32_t* ri2 = &sVh[sI[p1 + 8] * VSTRU + ub];
        const uint32_t* rj2 = &sVh[sJ[p1 + 8] * VSTRU + ub];

        // ---- A fragments: bf16 LDS.64 + HMUL2 ----
        uint32_t af[4][4];
        #pragma unroll
        for (int ks = 0; ks < 4; ks++) {
            uint2 vi = *(const uint2*)(ri1 + ks * 8);
            uint2 vj = *(const uint2*)(rj1 + ks * 8);
            af[ks][0] = mul_bf16x2(vi.x, vj.x);
            af[ks][2] = mul_bf16x2(vi.y, vj.y);
            vi = *(const uint2*)(ri2 + ks * 8);
            vj = *(const uint2*)(rj2 + ks * 8);
            af[ks][1] = mul_bf16x2(vi.x, vj.x);
            af[ks][3] = mul_bf16x2(vi.y, vj.y);
        }

        // ---- GEMM (W in registers) + fused score epilogue ----
        float s1 = 0.f, s2 = 0.f;
        #pragma unroll
        for (int nt = 0; nt < 8; nt++) {
            float d0 = 0.f, d1 = 0.f, d2 = 0.f, d3 = 0.f;
            #pragma unroll
            for (int ks = 0; ks < 4; ks++)
                mma_bf16(d0, d1, d2, d3,
                         af[ks][0], af[ks][1], af[ks][2], af[ks][3],
                         Wb[ks][nt].x, Wb[ks][nt].y);
            float4 ba = sBA4[nt * 4 + tig];   // broadcast LDS.128
            s1 += fmaxf(d0 + ba.x, 0.f) * ba.y + fmaxf(d1 + ba.z, 0.f) * ba.w;
            s2 += fmaxf(d2 + ba.x, 0.f) * ba.y + fmaxf(d3 + ba.z, 0.f) * ba.w;
        }
        s1 += __shfl_xor_sync(0xffffffffu, s1, 1);
        s1 += __shfl_xor_sync(0xffffffffu, s1, 2);
        s2 += __shfl_xor_sync(0xffffffffu, s2, 1);
        s2 += __shfl_xor_sync(0xffffffffu, s2, 2);

        // ---- pooling from the same A registers ----
        #pragma unroll
        for (int ks = 0; ks < 4; ks++) {
            float2 v;
            v = unpack_bf16x2(af[ks][0]);
            pooled[ks * 4 + 0] = fmaf(s1, v.x, pooled[ks * 4 + 0]);
            pooled[ks * 4 + 1] = fmaf(s1, v.y, pooled[ks * 4 + 1]);
            v = unpack_bf16x2(af[ks][2]);
            pooled[ks * 4 + 2] = fmaf(s1, v.x, pooled[ks * 4 + 2]);
            pooled[ks * 4 + 3] = fmaf(s1, v.y, pooled[ks * 4 + 3]);
            v = unpack_bf16x2(af[ks][1]);
            pooled[ks * 4 + 0] = fmaf(s2, v.x, pooled[ks * 4 + 0]);
            pooled[ks * 4 + 1] = fmaf(s2, v.y, pooled[ks * 4 + 1]);
            v = unpack_bf16x2(af[ks][3]);
            pooled[ks * 4 + 2] = fmaf(s2, v.x, pooled[ks * 4 + 2]);
            pooled[ks * 4 + 3] = fmaf(s2, v.y, pooled[ks * 4 + 3]);
        }
    }

    // ---- reduce pooled across gid lanes ----
    #pragma unroll
    for (int s = 0; s < 16; s++) {
        pooled[s] += __shfl_xor_sync(0xffffffffu, pooled[s], 4);
        pooled[s] += __shfl_xor_sync(0xffffffffu, pooled[s], 8);
        pooled[s] += __shfl_xor_sync(0xffffffffu, pooled[s], 16);
    }
    if (gid == 0) {
        #pragma unroll
        for (int ks = 0; ks < 4; ks++)
            *(float4*)&sPool[w][ks * 16 + 4 * tig] =
                make_float4(pooled[ks * 4 + 0], pooled[ks * 4 + 1],
                            pooled[ks * 4 + 2], pooled[ks * 4 + 3]);
    }
    __syncthreads();

    // ---- final: at_fm = (sum_w pooled) . p ; logit ; sigmoid ----
    if (tid < NK) {
        float v = 0.f;
        #pragma unroll
        for (int g = 0; g < 8; g++) v += sPool[g][tid];
        v *= __ldg(&pvec[tid]);
        #pragma unroll
        for (int off = 16; off >= 1; off >>= 1)
            v += __shfl_xor_sync(0xffffffffu, v, off);
        if ((tid & 31) == 0) sRed[tid >> 5] = v;
    }
    __syncthreads();

    if (tid == 0) {
        float logit = sRed[0] + sRed[1] + sFm1;
        out[b] = 1.f / (1.f + expf(-logit));
    }
}

extern "C" void kernel_launch(void* const* d_in, const int* in_sizes, int n_in,
                              void* d_out, int out_size) {
    const int*   x     = (const int*)  d_in[0];
    const float* emb_v = (const float*)d_in[1];
    const float* at_w  = (const float*)d_in[2];
    const float* at_b  = (const float*)d_in[3];
    const float* at_h  = (const float*)d_in[4];
    const float* pvec  = (const float*)d_in[5];
    const float* w0    = (const float*)d_in[6];
    const float* w1    = (const float*)d_in[7];
    float* out = (float*)d_out;

    wfrag_build<<<4, 256>>>(at_w);
    afm_mma_kernel<<<NB, 256>>>(x, emb_v, at_b, at_h, pvec, w0, w1, out);
}

// round 10
// speedup vs baseline: 1.8354x; 1.1704x over previous
#include <cuda_runtime.h>
#include <cuda_bf16.h>
#include <math.h>
#include <stdint.h>

#define NF    32
#define NB    2048
#define NK    64
#define NH    64
#define PAIRS 496
#define VSTRU 44     // uints per row: 16B-aligned, 16B-class = 11*row mod 8 (all 8 classes)
#define ZROW  32

// W fragment table, k-contiguous permutation: thread tig owns logical k [16tig,16tig+16)
// [ks(4)][nt(8)][lane(32)]
__device__ uint2 g_wfrag[4 * 8 * 32];

__device__ __forceinline__ uint32_t pack_bf16x2(float lo, float hi) {
    __nv_bfloat162 h = __floats2bfloat162_rn(lo, hi);
    return *reinterpret_cast<uint32_t*>(&h);
}
__device__ __forceinline__ float2 unpack_bf16x2(uint32_t u) {
    __nv_bfloat162 h = *reinterpret_cast<__nv_bfloat162*>(&u);
    return __bfloat1622float2(h);
}
__device__ __forceinline__ uint32_t mul_bf16x2(uint32_t a, uint32_t b) {
    __nv_bfloat162 ha = *reinterpret_cast<__nv_bfloat162*>(&a);
    __nv_bfloat162 hb = *reinterpret_cast<__nv_bfloat162*>(&b);
    __nv_bfloat162 hc = __hmul2(ha, hb);
    return *reinterpret_cast<uint32_t*>(&hc);
}

__device__ __forceinline__ void mma_bf16(float& d0, float& d1, float& d2, float& d3,
                                         uint32_t a0, uint32_t a1, uint32_t a2, uint32_t a3,
                                         uint32_t b0, uint32_t b1) {
    asm volatile(
        "mma.sync.aligned.m16n8k16.row.col.f32.bf16.bf16.f32 "
        "{%0,%1,%2,%3}, {%4,%5,%6,%7}, {%8,%9}, {%0,%1,%2,%3};"
        : "+f"(d0), "+f"(d1), "+f"(d2), "+f"(d3)
        : "r"(a0), "r"(a1), "r"(a2), "r"(a3), "r"(b0), "r"(b1));
}

// ---- pre-kernel: pack W with k-contiguous permutation ----
// mma ks-step s, slots {2tig,2tig+1} <- k = 16tig+4s+{0,1}; slots {2tig+8,2tig+9} <- +{2,3}
__global__ void wfrag_build(const float* __restrict__ at_w) {
    int idx  = blockIdx.x * 256 + threadIdx.x;   // 0..1023
    int lane = idx & 31;
    int tile = idx >> 5;
    int ks = tile >> 3, nt = tile & 7;
    int tig = lane & 3, gid = lane >> 2;
    int lk = 16 * tig + 4 * ks;
    int h  = nt * 8 + gid;
    uint2 v;
    v.x = pack_bf16x2(at_w[lk * NH + h],       at_w[(lk + 1) * NH + h]);
    v.y = pack_bf16x2(at_w[(lk + 2) * NH + h], at_w[(lk + 3) * NH + h]);
    g_wfrag[idx] = v;
}

__global__ __launch_bounds__(256, 2)
void afm_mma_kernel(const int*   __restrict__ x,      // [F, B]
                    const float* __restrict__ emb_v,  // [VOCAB, K]
                    const float* __restrict__ at_b,   // [H]
                    const float* __restrict__ at_h,   // [H]
                    const float* __restrict__ pvec,   // [K]
                    const float* __restrict__ w0,     // scalar
                    const float* __restrict__ w1,     // [VOCAB]
                    float*       __restrict__ out)    // [B]
{
    __shared__ uint32_t sVh[2][(NF + 1) * VSTRU];  // bf16x2 embeddings, 2 batches
    __shared__ float4   sBA4[32];
    __shared__ unsigned char sI[512], sJ[512];
    __shared__ float    sPool[8][NK];
    __shared__ float    sFm1[2], sRed[4];

    const int tid  = threadIdx.x;
    const int b0   = 2 * blockIdx.x;
    const int w    = tid >> 5;
    const int lane = tid & 31;
    const int gid  = lane >> 2;
    const int tig  = lane & 3;
    const int batch = w >> 2;        // warps 0-3 -> batch 0, 4-7 -> batch 1
    const int wloc  = w & 3;

    // ---- W fragments in registers (proven best) ----
    uint2 Wb[4][8];
    #pragma unroll
    for (int ks = 0; ks < 4; ks++)
        #pragma unroll
        for (int nt = 0; nt < 8; nt++)
            Wb[ks][nt] = __ldg(&g_wfrag[(ks * 8 + nt) * 32 + lane]);

    // ---- pair table (padded -> zero row) ----
    for (int p = tid; p < 512; p += 256) {
        if (p < PAIRS) {
            int pp = p, i = 0, off = 0;
            while (pp >= off + (NF - 1 - i)) { off += NF - 1 - i; i++; }
            sI[p] = (unsigned char)i;
            sJ[p] = (unsigned char)(i + 1 + pp - off);
        } else {
            sI[p] = ZROW; sJ[p] = ZROW;
        }
    }

    // ---- zero rows (both batches) ----
    if (tid < 2 * VSTRU) sVh[tid / VSTRU][ZROW * VSTRU + (tid % VSTRU)] = 0u;

    // ---- bias/at_h fragment table ----
    if (tid < 32) {
        int nt = tid >> 2, tg = tid & 3;
        int h0 = nt * 8 + 2 * tg;
        sBA4[tid] = make_float4(__ldg(&at_b[h0]),     __ldg(&at_h[h0]),
                                __ldg(&at_b[h0 + 1]), __ldg(&at_h[h0 + 1]));
    }

    // ---- gather embeddings for 2 batches, convert to bf16 ----
    for (int idx = tid; idx < 512; idx += 256) {
        int bt = idx >> 8, rem = idx & 255;
        int f = rem >> 3, q = rem & 7;           // 8 chunks of 8 floats per row
        int row = __ldg(&x[f * NB + b0 + bt]);
        const float4* src = (const float4*)emb_v + row * 16 + 2 * q;
        float4 v0 = __ldg(src), v1 = __ldg(src + 1);
        uint4 pk;
        pk.x = pack_bf16x2(v0.x, v0.y);
        pk.y = pack_bf16x2(v0.z, v0.w);
        pk.z = pack_bf16x2(v1.x, v1.y);
        pk.w = pack_bf16x2(v1.z, v1.w);
        *(uint4*)&sVh[bt][f * VSTRU + 4 * q] = pk;
    }

    // ---- first-order FM (warp 0 -> batch 0, warp 4 -> batch 1) ----
    if (wloc == 0) {
        int row = __ldg(&x[lane * NB + b0 + batch]);
        float v = __ldg(&w1[row]);
        #pragma unroll
        for (int off = 16; off >= 1; off >>= 1)
            v += __shfl_xor_sync(0xffffffffu, v, off);
        if (lane == 0) sFm1[batch] = v + __ldg(w0);
    }
    __syncthreads();

    float pooled[16];
    #pragma unroll
    for (int s = 0; s < 16; s++) pooled[s] = 0.f;

    const uint32_t* vb = sVh[batch];
    const int ub = 8 * tig;     // uint offset of this thread's 16 contiguous k

    #pragma unroll 2
    for (int t = 0; t < 8; t++) {
        const int p1 = t * 64 + wloc * 16 + gid;
        const uint32_t* ri1 = vb + sI[p1] * VSTRU + ub;
        const uint32_t* rj1 = vb + sJ[p1] * VSTRU + ub;
        const uint32_t* ri2 = vb + sI[p1 + 8] * VSTRU + ub;
        const uint32_t* rj2 = vb + sJ[p1 + 8] * VSTRU + ub;

        // ---- A fragments: 8 LDS.128 + 16 HMUL2 ----
        uint4 i0 = *(const uint4*)ri1, i1 = *(const uint4*)(ri1 + 4);
        uint4 j0 = *(const uint4*)rj1, j1 = *(const uint4*)(rj1 + 4);
        uint4 m0 = *(const uint4*)ri2, m1 = *(const uint4*)(ri2 + 4);
        uint4 n0 = *(const uint4*)rj2, n1 = *(const uint4*)(rj2 + 4);

        uint32_t af[4][4];
        af[0][0] = mul_bf16x2(i0.x, j0.x);  af[0][2] = mul_bf16x2(i0.y, j0.y);
        af[1][0] = mul_bf16x2(i0.z, j0.z);  af[1][2] = mul_bf16x2(i0.w, j0.w);
        af[2][0] = mul_bf16x2(i1.x, j1.x);  af[2][2] = mul_bf16x2(i1.y, j1.y);
        af[3][0] = mul_bf16x2(i1.z, j1.z);  af[3][2] = mul_bf16x2(i1.w, j1.w);
        af[0][1] = mul_bf16x2(m0.x, n0.x);  af[0][3] = mul_bf16x2(m0.y, n0.y);
        af[1][1] = mul_bf16x2(m0.z, n0.z);  af[1][3] = mul_bf16x2(m0.w, n0.w);
        af[2][1] = mul_bf16x2(m1.x, n1.x);  af[2][3] = mul_bf16x2(m1.y, n1.y);
        af[3][1] = mul_bf16x2(m1.z, n1.z);  af[3][3] = mul_bf16x2(m1.w, n1.w);

        // ---- GEMM (W in registers) + fused score epilogue ----
        float s1 = 0.f, s2 = 0.f;
        #pragma unroll
        for (int nt = 0; nt < 8; nt++) {
            float d0 = 0.f, d1 = 0.f, d2 = 0.f, d3 = 0.f;
            #pragma unroll
            for (int ks = 0; ks < 4; ks++)
                mma_bf16(d0, d1, d2, d3,
                         af[ks][0], af[ks][1], af[ks][2], af[ks][3],
                         Wb[ks][nt].x, Wb[ks][nt].y);
            float4 ba = sBA4[nt * 4 + tig];
            s1 += fmaxf(d0 + ba.x, 0.f) * ba.y + fmaxf(d1 + ba.z, 0.f) * ba.w;
            s2 += fmaxf(d2 + ba.x, 0.f) * ba.y + fmaxf(d3 + ba.z, 0.f) * ba.w;
        }
        s1 += __shfl_xor_sync(0xffffffffu, s1, 1);
        s1 += __shfl_xor_sync(0xffffffffu, s1, 2);
        s2 += __shfl_xor_sync(0xffffffffu, s2, 1);
        s2 += __shfl_xor_sync(0xffffffffu, s2, 2);

        // ---- pooling from the same A registers (k = 16tig + 4ks + {0..3}) ----
        #pragma unroll
        for (int ks = 0; ks < 4; ks++) {
            float2 v;
            v = unpack_bf16x2(af[ks][0]);
            pooled[ks * 4 + 0] = fmaf(s1, v.x, pooled[ks * 4 + 0]);
            pooled[ks * 4 + 1] = fmaf(s1, v.y, pooled[ks * 4 + 1]);
            v = unpack_bf16x2(af[ks][2]);
            pooled[ks * 4 + 2] = fmaf(s1, v.x, pooled[ks * 4 + 2]);
            pooled[ks * 4 + 3] = fmaf(s1, v.y, pooled[ks * 4 + 3]);
            v = unpack_bf16x2(af[ks][1]);
            pooled[ks * 4 + 0] = fmaf(s2, v.x, pooled[ks * 4 + 0]);
            pooled[ks * 4 + 1] = fmaf(s2, v.y, pooled[ks * 4 + 1]);
            v = unpack_bf16x2(af[ks][3]);
            pooled[ks * 4 + 2] = fmaf(s2, v.x, pooled[ks * 4 + 2]);
            pooled[ks * 4 + 3] = fmaf(s2, v.y, pooled[ks * 4 + 3]);
        }
    }

    // ---- reduce pooled across gid lanes; lanes tig hold k in [16tig, 16tig+16) ----
    #pragma unroll
    for (int s = 0; s < 16; s++) {
        pooled[s] += __shfl_xor_sync(0xffffffffu, pooled[s], 4);
        pooled[s] += __shfl_xor_sync(0xffffffffu, pooled[s], 8);
        pooled[s] += __shfl_xor_sync(0xffffffffu, pooled[s], 16);
    }
    if (gid == 0) {
        #pragma unroll
        for (int ks = 0; ks < 4; ks++)
            *(float4*)&sPool[w][16 * tig + 4 * ks] =
                make_float4(pooled[ks * 4 + 0], pooled[ks * 4 + 1],
                            pooled[ks * 4 + 2], pooled[ks * 4 + 3]);
    }
    __syncthreads();

    // ---- final: per batch, at_fm = (sum of 4 warps' pooled) . p ; sigmoid ----
    if (tid < 128) {
        int bt = tid >> 6, k = tid & 63;
        float v = sPool[bt * 4 + 0][k] + sPool[bt * 4 + 1][k] +
                  sPool[bt * 4 + 2][k] + sPool[bt * 4 + 3][k];
        v *= __ldg(&pvec[k]);
        #pragma unroll
        for (int off = 16; off >= 1; off >>= 1)
            v += __shfl_xor_sync(0xffffffffu, v, off);
        if (lane == 0) sRed[w] = v;   // warps 0,1 -> batch0; 2,3 -> batch1
    }
    __syncthreads();

    if (tid < 2) {
        float logit = sRed[2 * tid] + sRed[2 * tid + 1] + sFm1[tid];
        out[b0 + tid] = 1.f / (1.f + expf(-logit));
    }
}

extern "C" void kernel_launch(void* const* d_in, const int* in_sizes, int n_in,
                              void* d_out, int out_size) {
    const int*   x     = (const int*)  d_in[0];
    const float* emb_v = (const float*)d_in[1];
    const float* at_w  = (const float*)d_in[2];
    const float* at_b  = (const float*)d_in[3];
    const float* at_h  = (const float*)d_in[4];
    const float* pvec  = (const float*)d_in[5];
    const float* w0    = (const float*)d_in[6];
    const float* w1    = (const float*)d_in[7];
    float* out = (float*)d_out;

    wfrag_build<<<4, 256>>>(at_w);
    afm_mma_kernel<<<NB / 2, 256>>>(x, emb_v, at_b, at_h, pvec, w0, w1, out);
}